// round 5
// baseline (speedup 1.0000x reference)
#include <cuda_runtime.h>

#define NBATCH 4
#define NQ 2048
#define NF 16384
#define CDIM 768
#define SCALEF 0.57735026918962576f  // 1/sqrt(3)

#define TQ 16        // query rows per CTA
#define CK 64        // key chunk size
#define TPB 192      // threads: each owns 4 output columns (192*4 = 768)
#define SPLITS 4     // split-K over keys
#define KPS (NF / SPLITS)      // 4096 keys per split
#define NCHUNK (KPS / CK)      // 64 chunks
#define PV_PER_THREAD 6        // ceil(CK*TQ / TPB) = ceil(1024/192)

// Scratch: projected q/k (padded float4), split-K partials.
__device__ __align__(16) float4 g_qp[NBATCH * NQ];
__device__ __align__(16) float4 g_kp[NBATCH * NF];
__device__ __align__(16) float g_num[(size_t)SPLITS * NBATCH * NQ * CDIM];
__device__ float g_den[SPLITS * NBATCH * NQ];

// ---- packed f32x2 helpers (FFMA2: 2x fp32 FMA throughput, PTX-only) ----
__device__ __forceinline__ unsigned long long pack2(float lo, float hi) {
    unsigned long long u;
    asm("mov.b64 %0, {%1, %2};" : "=l"(u) : "f"(lo), "f"(hi));
    return u;
}
__device__ __forceinline__ void fma2(unsigned long long& a, unsigned long long b,
                                     unsigned long long c) {
    asm("fma.rn.f32x2 %0, %1, %2, %0;" : "+l"(a) : "l"(b), "l"(c));
}
__device__ __forceinline__ void unpack2(unsigned long long a, float& lo, float& hi) {
    asm("mov.b64 {%0, %1}, %2;" : "=f"(lo), "=f"(hi) : "l"(a));
}

// ---- Kernel 1: tiny 3x3 projections + ReLU for q and k ----
__global__ void proj_kernel(const float* __restrict__ q, const float* __restrict__ k,
                            const float* __restrict__ W1, const float* __restrict__ b1,
                            const float* __restrict__ W2, const float* __restrict__ b2) {
    int i = blockIdx.x * blockDim.x + threadIdx.x;
    const int nq = NBATCH * NQ;
    const int nf = NBATCH * NF;
    if (i < nq) {
        float x0 = q[3 * i], x1 = q[3 * i + 1], x2 = q[3 * i + 2];
        float4 o;
        o.x = fmaxf(0.f, fmaf(W1[0], x0, fmaf(W1[1], x1, fmaf(W1[2], x2, b1[0]))));
        o.y = fmaxf(0.f, fmaf(W1[3], x0, fmaf(W1[4], x1, fmaf(W1[5], x2, b1[1]))));
        o.z = fmaxf(0.f, fmaf(W1[6], x0, fmaf(W1[7], x1, fmaf(W1[8], x2, b1[2]))));
        o.w = 0.f;
        g_qp[i] = o;
    } else if (i < nq + nf) {
        int j = i - nq;
        float x0 = k[3 * j], x1 = k[3 * j + 1], x2 = k[3 * j + 2];
        float4 o;
        o.x = fmaxf(0.f, fmaf(W2[0], x0, fmaf(W2[1], x1, fmaf(W2[2], x2, b2[0]))));
        o.y = fmaxf(0.f, fmaf(W2[3], x0, fmaf(W2[4], x1, fmaf(W2[5], x2, b2[1]))));
        o.z = fmaxf(0.f, fmaf(W2[6], x0, fmaf(W2[7], x1, fmaf(W2[8], x2, b2[2]))));
        o.w = 0.f;
        g_kp[j] = o;
    }
}

// ---- Kernel 2: single-pass unnormalized attention, split-K ----
// No max subtraction: scores are bounded (ReLU'd operands, D=3), exp stays
// finite in fp32. Accumulate num = sum(e*v), den = sum(e); normalize later.
// Grid: (NQ/TQ, NBATCH, SPLITS). Thread t owns 4 columns [4t, 4t+4).
__global__ void __launch_bounds__(TPB, 3) attn_kernel(const float* __restrict__ v) {
    const int b = blockIdx.y;
    const int r0 = blockIdx.x * TQ;
    const int split = blockIdx.z;
    const int s0 = split * KPS;

    const float4* __restrict__ kp = g_kp + b * NF + s0;
    const float4* __restrict__ qpb = g_qp + b * NQ + r0;
    const float* __restrict__ vb = v + ((size_t)b * NF + s0) * CDIM;

    __shared__ __align__(16) float4 qp_s[TQ];
    __shared__ __align__(16) float p_s[2][CK][TQ];  // double-buffered, p_s[buf][key][row]
    __shared__ float lred[TPB];

    const int tid = threadIdx.x;
    if (tid < TQ) qp_s[tid] = qpb[tid];
    __syncthreads();

    const int row = tid & 15;           // 192 % 16 == 0: fixed row per thread
    const float4 qv = qp_s[row];
    float lpart = 0.f;

    // Prologue: fill p buffer 0 for chunk 0.
    #pragma unroll
    for (int j = 0; j < PV_PER_THREAD; j++) {
        int idx = tid + j * TPB;
        if (idx < CK * TQ) {
            float4 kv = kp[idx >> 4];
            float e = __expf((qv.x * kv.x + qv.y * kv.y + qv.z * kv.z) * SCALEF);
            p_s[0][idx >> 4][row] = e;
            lpart += e;
        }
    }
    __syncthreads();

    unsigned long long acc[8][4];
    #pragma unroll
    for (int g = 0; g < 8; g++)
        #pragma unroll
        for (int c = 0; c < 4; c++) acc[g][c] = 0ull;

    const int c0 = tid << 2;
    int buf = 0;

    for (int c = 0; c < NCHUNK; ++c) {
        const bool has_next = (c + 1 < NCHUNK);

        // Stage 1: issue kp loads for next chunk (latency hidden under fma sweep).
        float4 kvb[PV_PER_THREAD];
        if (has_next) {
            const float4* __restrict__ kpn = kp + (size_t)(c + 1) * CK;
            #pragma unroll
            for (int j = 0; j < PV_PER_THREAD; j++) {
                int idx = tid + j * TPB;
                if (idx < CK * TQ) kvb[j] = kpn[idx >> 4];
            }
        }

        // Stage 2: fma sweep over current chunk's 64 keys.
        const float* __restrict__ vch = vb + (size_t)c * CK * CDIM + c0;
        #pragma unroll 4
        for (int mm = 0; mm < CK; mm++) {
            float4 vv = *reinterpret_cast<const float4*>(vch + (size_t)mm * CDIM);
            unsigned long long vx = pack2(vv.x, vv.x);
            unsigned long long vy = pack2(vv.y, vv.y);
            unsigned long long vz = pack2(vv.z, vv.z);
            unsigned long long vw = pack2(vv.w, vv.w);
            const ulonglong2* pp = reinterpret_cast<const ulonglong2*>(&p_s[buf][mm][0]);
            #pragma unroll
            for (int g = 0; g < 4; g++) {
                ulonglong2 p2 = pp[g];  // rows (4g,4g+1) and (4g+2,4g+3)
                fma2(acc[2 * g][0], p2.x, vx);
                fma2(acc[2 * g][1], p2.x, vy);
                fma2(acc[2 * g][2], p2.x, vz);
                fma2(acc[2 * g][3], p2.x, vw);
                fma2(acc[2 * g + 1][0], p2.y, vx);
                fma2(acc[2 * g + 1][1], p2.y, vy);
                fma2(acc[2 * g + 1][2], p2.y, vz);
                fma2(acc[2 * g + 1][3], p2.y, vw);
            }
        }

        // Stage 3: compute next chunk's exps into the other buffer.
        if (has_next) {
            #pragma unroll
            for (int j = 0; j < PV_PER_THREAD; j++) {
                int idx = tid + j * TPB;
                if (idx < CK * TQ) {
                    float4 kv = kvb[j];
                    float e = __expf((qv.x * kv.x + qv.y * kv.y + qv.z * kv.z) * SCALEF);
                    p_s[buf ^ 1][idx >> 4][row] = e;
                    lpart += e;
                }
            }
        }
        __syncthreads();
        buf ^= 1;
    }

    // Denominator: reduce 12 partials per row.
    lred[tid] = lpart;
    __syncthreads();
    if (tid < TQ) {
        float l = 0.f;
        #pragma unroll
        for (int j = 0; j < 12; j++) l += lred[tid + (j << 4)];
        g_den[((size_t)split * NBATCH + b) * NQ + r0 + tid] = l;
    }

    // Numerator partials to scratch.
    float* orow = g_num + (((size_t)split * NBATCH + b) * NQ + r0) * CDIM + c0;
    #pragma unroll
    for (int g = 0; g < 8; g++) {
        float lo0, hi0, lo1, hi1, lo2, hi2, lo3, hi3;
        unpack2(acc[g][0], lo0, hi0);
        unpack2(acc[g][1], lo1, hi1);
        unpack2(acc[g][2], lo2, hi2);
        unpack2(acc[g][3], lo3, hi3);
        *reinterpret_cast<float4*>(orow + (size_t)(2 * g) * CDIM) =
            make_float4(lo0, lo1, lo2, lo3);
        *reinterpret_cast<float4*>(orow + (size_t)(2 * g + 1) * CDIM) =
            make_float4(hi0, hi1, hi2, hi3);
    }
}

// ---- Kernel 3: combine split-K partials and normalize ----
__global__ void combine_kernel(float* __restrict__ out) {
    const size_t i = (size_t)blockIdx.x * blockDim.x + threadIdx.x;  // float4 index
    const size_t total4 = (size_t)NBATCH * NQ * CDIM / 4;
    if (i >= total4) return;
    const size_t rowi = i / (CDIM / 4);  // global row: b*NQ + r
    const size_t stride4 = (size_t)NBATCH * NQ * CDIM / 4;

    float4 n0 = reinterpret_cast<const float4*>(g_num)[i];
    float4 n1 = reinterpret_cast<const float4*>(g_num)[i + stride4];
    float4 n2 = reinterpret_cast<const float4*>(g_num)[i + 2 * stride4];
    float4 n3 = reinterpret_cast<const float4*>(g_num)[i + 3 * stride4];
    float den = g_den[rowi] + g_den[rowi + (size_t)NBATCH * NQ] +
                g_den[rowi + 2 * (size_t)NBATCH * NQ] +
                g_den[rowi + 3 * (size_t)NBATCH * NQ];
    float inv = 1.f / den;
    float4 o;
    o.x = (n0.x + n1.x + n2.x + n3.x) * inv;
    o.y = (n0.y + n1.y + n2.y + n3.y) * inv;
    o.z = (n0.z + n1.z + n2.z + n3.z) * inv;
    o.w = (n0.w + n1.w + n2.w + n3.w) * inv;
    reinterpret_cast<float4*>(out)[i] = o;
}

extern "C" void kernel_launch(void* const* d_in, const int* in_sizes, int n_in,
                              void* d_out, int out_size) {
    const float* q  = (const float*)d_in[0];
    const float* k  = (const float*)d_in[1];
    const float* v  = (const float*)d_in[2];
    const float* W1 = (const float*)d_in[3];
    const float* b1 = (const float*)d_in[4];
    const float* W2 = (const float*)d_in[5];
    const float* b2 = (const float*)d_in[6];
    float* out = (float*)d_out;

    const int total = NBATCH * (NQ + NF);
    proj_kernel<<<(total + 255) / 256, 256>>>(q, k, W1, b1, W2, b2);

    dim3 grid(NQ / TQ, NBATCH, SPLITS);
    attn_kernel<<<grid, TPB>>>(v);

    const int total4 = NBATCH * NQ * CDIM / 4;
    combine_kernel<<<(total4 + 255) / 256, 256>>>(out);
}

// round 7
// speedup vs baseline: 3.7990x; 3.7990x over previous
#include <cuda_runtime.h>
#include <cstdint>

#define NBATCH 4
#define NQ 2048
#define NF 16384
#define CDIM 768
#define SCALEF 0.57735026918962576f

// ---- GEMM tiling ----
#define BM 128
#define BN 128
#define BK 32
#define STAGES 3
#define LDT 36                      // padded row length (floats) for both tiles
#define TILE_FLOATS (BM * LDT)      // 4608
#define STAGE_FLOATS (2 * TILE_FLOATS)
#define GEMM_SMEM (STAGES * STAGE_FLOATS * 4)   // 110592 B
#define NCH (NF / BK)               // 512

// ---- scratch (static device memory; no allocations) ----
__device__ __align__(16) float4 g_qp[NBATCH * NQ];
__device__ __align__(16) float4 g_kp[NBATCH * NF];
__device__ __align__(16) float g_p[(size_t)NBATCH * NQ * NF];       // exp scores, tf32-rounded
__device__ __align__(16) float g_vt[(size_t)NBATCH * CDIM * NF];    // V^T, tf32-rounded
__device__ float g_iden[NBATCH * NQ];                               // 1/denominator

// ---------- helpers ----------
__device__ __forceinline__ uint32_t smem_u32(const void* p) {
    uint32_t a;
    asm("{ .reg .u64 t; cvta.to.shared.u64 t, %1; cvt.u32.u64 %0, t; }" : "=r"(a) : "l"(p));
    return a;
}
__device__ __forceinline__ float tf32r(float x) {
    uint32_t u;
    asm("cvt.rna.tf32.f32 %0, %1;" : "=r"(u) : "f"(x));
    return __uint_as_float(u);
}
__device__ __forceinline__ uint32_t lds32(uint32_t a) {
    uint32_t v;
    asm volatile("ld.shared.b32 %0, [%1];" : "=r"(v) : "r"(a));
    return v;
}
__device__ __forceinline__ void cp_async16(uint32_t saddr, const float* gaddr) {
    asm volatile("cp.async.cg.shared.global [%0], [%1], 16;" :: "r"(saddr), "l"(gaddr));
}
#define CP_COMMIT() asm volatile("cp.async.commit_group;" ::: "memory")
#define CP_WAIT2()  asm volatile("cp.async.wait_group 2;" ::: "memory")

__device__ __forceinline__ void mma_tf32(float* d, const uint32_t* a, const uint32_t* b) {
    asm volatile(
        "mma.sync.aligned.m16n8k8.row.col.f32.tf32.tf32.f32 "
        "{%0,%1,%2,%3}, {%4,%5,%6,%7}, {%8,%9}, {%0,%1,%2,%3};"
        : "+f"(d[0]), "+f"(d[1]), "+f"(d[2]), "+f"(d[3])
        : "r"(a[0]), "r"(a[1]), "r"(a[2]), "r"(a[3]), "r"(b[0]), "r"(b[1]));
}

// ---- Kernel 1: 3x3 projections + ReLU (q pre-scaled by 1/sqrt(3)) ----
__global__ void proj_kernel(const float* __restrict__ q, const float* __restrict__ k,
                            const float* __restrict__ W1, const float* __restrict__ b1,
                            const float* __restrict__ W2, const float* __restrict__ b2) {
    int i = blockIdx.x * blockDim.x + threadIdx.x;
    const int nq = NBATCH * NQ, nf = NBATCH * NF;
    if (i < nq) {
        float x0 = q[3 * i], x1 = q[3 * i + 1], x2 = q[3 * i + 2];
        float4 o;
        o.x = SCALEF * fmaxf(0.f, fmaf(W1[0], x0, fmaf(W1[1], x1, fmaf(W1[2], x2, b1[0]))));
        o.y = SCALEF * fmaxf(0.f, fmaf(W1[3], x0, fmaf(W1[4], x1, fmaf(W1[5], x2, b1[1]))));
        o.z = SCALEF * fmaxf(0.f, fmaf(W1[6], x0, fmaf(W1[7], x1, fmaf(W1[8], x2, b1[2]))));
        o.w = 0.f;
        g_qp[i] = o;
    } else if (i < nq + nf) {
        int j = i - nq;
        float x0 = k[3 * j], x1 = k[3 * j + 1], x2 = k[3 * j + 2];
        float4 o;
        o.x = fmaxf(0.f, fmaf(W2[0], x0, fmaf(W2[1], x1, fmaf(W2[2], x2, b2[0]))));
        o.y = fmaxf(0.f, fmaf(W2[3], x0, fmaf(W2[4], x1, fmaf(W2[5], x2, b2[1]))));
        o.z = fmaxf(0.f, fmaf(W2[6], x0, fmaf(W2[7], x1, fmaf(W2[8], x2, b2[2]))));
        o.w = 0.f;
        g_kp[j] = o;
    }
}

// ---- Kernel 2: E[b][m][:] = exp(qp . kp), tf32-rounded; g_iden = 1/sum(exp) ----
// Grid (NQ, NBATCH), 256 threads. Each thread handles 4 keys per iteration.
__global__ void exp_kernel() {
    const int m = blockIdx.x, b = blockIdx.y;
    const int tid = threadIdx.x;
    const float4 qv = g_qp[b * NQ + m];
    const float4* __restrict__ kp = g_kp + b * NF;
    float4* __restrict__ prow =
        reinterpret_cast<float4*>(g_p + ((size_t)b * NQ + m) * NF);

    float part = 0.f;
    #pragma unroll
    for (int j = 0; j < NF / 4 / 256; ++j) {
        int i4 = tid + j * 256;              // group of 4 keys
        float4 k0 = kp[4 * i4 + 0];
        float4 k1 = kp[4 * i4 + 1];
        float4 k2 = kp[4 * i4 + 2];
        float4 k3 = kp[4 * i4 + 3];
        float e0 = __expf(qv.x * k0.x + qv.y * k0.y + qv.z * k0.z);
        float e1 = __expf(qv.x * k1.x + qv.y * k1.y + qv.z * k1.z);
        float e2 = __expf(qv.x * k2.x + qv.y * k2.y + qv.z * k2.z);
        float e3 = __expf(qv.x * k3.x + qv.y * k3.y + qv.z * k3.z);
        part += (e0 + e1) + (e2 + e3);
        prow[i4] = make_float4(tf32r(e0), tf32r(e1), tf32r(e2), tf32r(e3));
    }

    __shared__ float red[256];
    red[tid] = part;
    __syncthreads();
    #pragma unroll
    for (int s = 128; s > 0; s >>= 1) {
        if (tid < s) red[tid] += red[tid + s];
        __syncthreads();
    }
    if (tid == 0) g_iden[b * NQ + m] = 1.f / red[0];
}

// ---- Kernel 3: V transpose to [b][c][k], tf32-rounded ----
__global__ void transpose_v(const float* __restrict__ v) {
    __shared__ float tile[32][33];
    const int b = blockIdx.z, k0 = blockIdx.x << 5, c0 = blockIdx.y << 5;
    const int x = threadIdx.x, y = threadIdx.y;
    const float* vb = v + ((size_t)b * NF + k0) * CDIM + c0;
    #pragma unroll
    for (int j = 0; j < 32; j += 8) tile[y + j][x] = vb[(size_t)(y + j) * CDIM + x];
    __syncthreads();
    float* o = g_vt + ((size_t)b * CDIM + c0) * NF + k0;
    #pragma unroll
    for (int j = 0; j < 32; j += 8) o[(size_t)(y + j) * NF + x] = tf32r(tile[x][y + j]);
}

// ---- Kernel 4: tf32 mma.sync GEMM: out = (E @ V) * iden ----
// Grid (CDIM/BN=6, NQ/BM=16, NBATCH). 128 threads = 4 warps, warp tile 64x64.
__global__ void __launch_bounds__(128, 1) gemm_kernel(float* __restrict__ out) {
    extern __shared__ float sm[];
    const uint32_t sbase = smem_u32(sm);
    const int b = blockIdx.z;
    const int n0 = blockIdx.x * BN;
    const int m0 = blockIdx.y * BM;
    const int tid = threadIdx.x, lane = tid & 31, wid = tid >> 5;
    const int warp_m = wid & 1, warp_n = wid >> 1;

    const float* __restrict__ Ag = g_p + ((size_t)b * NQ + m0) * NF;
    const float* __restrict__ Bg = g_vt + ((size_t)b * CDIM + n0) * NF;

    // stage loader: 8 float4 per thread for A, 8 for B (coalesced 128B/8 threads)
    auto load_stage = [&](int s, int k0) {
        const uint32_t As = sbase + (uint32_t)s * STAGE_FLOATS * 4;
        const uint32_t Bs = As + TILE_FLOATS * 4;
        #pragma unroll
        for (int j = 0; j < 8; ++j) {
            int flat = tid + 128 * j;       // 0..1023
            int row = flat >> 3, k4 = flat & 7;
            cp_async16(As + (uint32_t)(row * LDT + k4 * 4) * 4,
                       Ag + (size_t)row * NF + k0 + k4 * 4);
        }
        #pragma unroll
        for (int j = 0; j < 8; ++j) {
            int flat = tid + 128 * j;
            int row = flat >> 3, k4 = flat & 7;
            cp_async16(Bs + (uint32_t)(row * LDT + k4 * 4) * 4,
                       Bg + (size_t)row * NF + k0 + k4 * 4);
        }
        CP_COMMIT();
    };

    #pragma unroll
    for (int s = 0; s < STAGES; ++s) load_stage(s, s * BK);

    float acc[4][8][4];
    #pragma unroll
    for (int ma = 0; ma < 4; ++ma)
        #pragma unroll
        for (int na = 0; na < 8; ++na)
            #pragma unroll
            for (int r = 0; r < 4; ++r) acc[ma][na][r] = 0.f;

    const int g = lane >> 2, t = lane & 3;

    for (int c = 0; c < NCH; ++c) {
        CP_WAIT2();
        __syncthreads();
        const int s = c % STAGES;
        const uint32_t As = sbase + (uint32_t)s * STAGE_FLOATS * 4;
        const uint32_t Bs = As + TILE_FLOATS * 4;

        #pragma unroll
        for (int ks = 0; ks < BK / 8; ++ks) {
            uint32_t af[4][4], bf[8][2];
            #pragma unroll
            for (int ma = 0; ma < 4; ++ma) {
                const int row = warp_m * 64 + ma * 16 + g;
                const int col = ks * 8 + t;
                af[ma][0] = lds32(As + (uint32_t)(row * LDT + col) * 4);
                af[ma][1] = lds32(As + (uint32_t)((row + 8) * LDT + col) * 4);
                af[ma][2] = lds32(As + (uint32_t)(row * LDT + col + 4) * 4);
                af[ma][3] = lds32(As + (uint32_t)((row + 8) * LDT + col + 4) * 4);
            }
            #pragma unroll
            for (int na = 0; na < 8; ++na) {
                const int nrow = warp_n * 64 + na * 8 + g;
                const int kk = ks * 8 + t;
                bf[na][0] = lds32(Bs + (uint32_t)(nrow * LDT + kk) * 4);
                bf[na][1] = lds32(Bs + (uint32_t)(nrow * LDT + kk + 4) * 4);
            }
            #pragma unroll
            for (int ma = 0; ma < 4; ++ma)
                #pragma unroll
                for (int na = 0; na < 8; ++na)
                    mma_tf32(acc[ma][na], af[ma], bf[na]);
        }
        __syncthreads();
        if (c + STAGES < NCH) load_stage(s, (c + STAGES) * BK);
        else CP_COMMIT();  // keep group count aligned
    }

    // epilogue: scale by 1/den, write float2 pairs
    #pragma unroll
    for (int ma = 0; ma < 4; ++ma) {
        const int r0 = m0 + warp_m * 64 + ma * 16 + g;
        const int r1 = r0 + 8;
        const float i0 = g_iden[b * NQ + r0];
        const float i1 = g_iden[b * NQ + r1];
        #pragma unroll
        for (int na = 0; na < 8; ++na) {
            const int n = n0 + warp_n * 64 + na * 8 + 2 * t;
            float2 o0 = make_float2(acc[ma][na][0] * i0, acc[ma][na][1] * i0);
            float2 o1 = make_float2(acc[ma][na][2] * i1, acc[ma][na][3] * i1);
            *reinterpret_cast<float2*>(out + ((size_t)b * NQ + r0) * CDIM + n) = o0;
            *reinterpret_cast<float2*>(out + ((size_t)b * NQ + r1) * CDIM + n) = o1;
        }
    }
}

extern "C" void kernel_launch(void* const* d_in, const int* in_sizes, int n_in,
                              void* d_out, int out_size) {
    const float* q  = (const float*)d_in[0];
    const float* k  = (const float*)d_in[1];
    const float* v  = (const float*)d_in[2];
    const float* W1 = (const float*)d_in[3];
    const float* b1 = (const float*)d_in[4];
    const float* W2 = (const float*)d_in[5];
    const float* b2 = (const float*)d_in[6];
    float* out = (float*)d_out;

    const int total = NBATCH * (NQ + NF);
    proj_kernel<<<(total + 255) / 256, 256>>>(q, k, W1, b1, W2, b2);

    exp_kernel<<<dim3(NQ, NBATCH), 256>>>();

    transpose_v<<<dim3(NF / 32, CDIM / 32, NBATCH), dim3(32, 8)>>>(v);

    cudaFuncSetAttribute(gemm_kernel, cudaFuncAttributeMaxDynamicSharedMemorySize, GEMM_SMEM);
    gemm_kernel<<<dim3(CDIM / BN, NQ / BM, NBATCH), 128, GEMM_SMEM>>>(out);
}